// round 17
// baseline (speedup 1.0000x reference)
#include <cuda_runtime.h>
#include <cuda_bf16.h>
#include <cooperative_groups.h>
namespace cg = cooperative_groups;

#define BB    64
#define LL    4096
#define DD    256
#define VOCAB 33
#define NT    512
#define NWARP 16
#define GRID  128

__device__ int   gcnt[BB][VOCAB];
__device__ float g_M1[VOCAB * DD];     // emb @ W1
__device__ float g_h[BB * DD];         // layer-1 activations

__global__ __launch_bounds__(NT, 1)
void prot_net_coop(const int* __restrict__ X,
                   const int* __restrict__ vlen,
                   const float* __restrict__ emb,
                   const float* __restrict__ W1,
                   const float* __restrict__ b1,
                   const float* __restrict__ W2,
                   const float* __restrict__ b2,
                   float* __restrict__ out)
{
    __shared__ union SMem {
        struct { int wh[NWARP][VOCAB]; } a;          // hist
        struct {                                      // M1 tile (4 cols, all v)
            float embs[VOCAB * DD];                   // 33.8 KB
            float w1s[DD * 4];                        // 4 KB, [k][c]
            float mp[264];                            // k-split partials
        } m;
        struct {                                      // B1: h half
            float cnt[VOCAB];
            float hp[4][128];
        } b1;
        struct {                                      // B2: GEMM tile
            float  h[4][DD];                          // 4 KB
            float4 part[16][4][8];                    // 8 KB
        } b2;
    } sm;

    const int bid = blockIdx.x;
    const int tid = threadIdx.x;

    // ================= PHASE A =================
    if (bid < 64) {
        // ---- full-row histogram (R10-proven) ----
        const int warp = tid >> 5;
        const int row  = bid;
        const int4 xa = ((const int4*)X)[row * (LL / 4) + tid];
        const int4 xb = ((const int4*)X)[row * (LL / 4) + 512 + tid];
        const int  vl = vlen[row];
        const int  la = tid * 4;
        const int  lb = 2048 + tid * 4;

        for (int i = tid; i < NWARP * VOCAB; i += NT)
            (&sm.a.wh[0][0])[i] = 0;
        __syncthreads();

        if (la < vl) {
            atomicAdd(&sm.a.wh[warp][xa.x], 1);
            if (la + 1 < vl) atomicAdd(&sm.a.wh[warp][xa.y], 1);
            if (la + 2 < vl) atomicAdd(&sm.a.wh[warp][xa.z], 1);
            if (la + 3 < vl) atomicAdd(&sm.a.wh[warp][xa.w], 1);
        }
        if (lb < vl) {
            atomicAdd(&sm.a.wh[warp][xb.x], 1);
            if (lb + 1 < vl) atomicAdd(&sm.a.wh[warp][xb.y], 1);
            if (lb + 2 < vl) atomicAdd(&sm.a.wh[warp][xb.z], 1);
            if (lb + 3 < vl) atomicAdd(&sm.a.wh[warp][xb.w], 1);
        }
        __syncthreads();

        if (tid < VOCAB) {
            int s = 0;
            #pragma unroll
            for (int w = 0; w < NWARP; w++) s += sm.a.wh[w][tid];
            gcnt[row][tid] = s;
        }
        __syncthreads();
    } else {
        // ---- M1[:, c0..c0+3] for ALL v; W1 tile read once globally ----
        const int j  = bid - 64;                     // f4-col index 0..63
        const int c0 = j * 4;

        // stage emb (coalesced float4) and the 4-col W1 tile
        for (int i = tid; i < VOCAB * (DD / 4); i += NT)
            ((float4*)sm.m.embs)[i] = ((const float4*)emb)[i];
        if (tid < DD)
            ((float4*)sm.m.w1s)[tid] = ((const float4*)W1)[tid * (DD / 4) + j];
        __syncthreads();

        // compute: t<264 : c=t&3, k2=(t>>2)&1, v=t>>3 ; 128-k partial dot
        if (tid < 264) {
            const int c  = tid & 3;
            const int k2 = (tid >> 2) & 1;
            const int v  = tid >> 3;
            const float* ev = sm.m.embs + v * DD + k2 * 128;
            const float* wv = sm.m.w1s + k2 * 128 * 4 + c;
            float a = 0.f;
            #pragma unroll 8
            for (int kk = 0; kk < 128; kk++)
                a = fmaf(ev[kk], wv[kk * 4], a);
            sm.m.mp[tid] = a;
        }
        __syncthreads();

        if (tid < 132) {
            const int v = tid >> 2, c = tid & 3;
            g_M1[v * DD + c0 + c] = sm.m.mp[v * 8 + c] + sm.m.mp[v * 8 + 4 + c];
        }
        __syncthreads();
    }

    cg::this_grid().sync();

    // ================= PHASE B1: h, (row, 128-dim half) =================
    {
        const int row = bid >> 1;
        const int dh  = bid & 1;

        if (tid < VOCAB) sm.b1.cnt[tid] = (float)gcnt[row][tid];
        __syncthreads();

        // 4-way vocab split: groups [0,9) [9,17) [17,25) [25,33)
        {
            const int d = tid & 127;
            const int q = tid >> 7;
            const int v0 = (q == 0) ? 0 : 9 + 8 * (q - 1);
            const int v1 = (q == 0) ? 9 : v0 + 8;
            float a = (q == 0) ? b1[dh * 128 + d] : 0.f;
            for (int v = v0; v < v1; v++)
                a = fmaf(sm.b1.cnt[v], g_M1[v * DD + dh * 128 + d], a);  // coalesced
            sm.b1.hp[q][d] = a;
        }
        __syncthreads();

        if (tid < 128)
            g_h[row * DD + dh * 128 + tid] =
                fmaxf(sm.b1.hp[0][tid] + sm.b1.hp[1][tid] +
                      sm.b1.hp[2][tid] + sm.b1.hp[3][tid], 0.f);
        __syncthreads();
    }

    cg::this_grid().sync();

    // ================= PHASE B2: 4-row x 32-col GEMM tiles =================
    {
        const int r0  = (bid >> 3) * 4;
        const int cg_ = bid & 7;
        const int c0  = cg_ * 32;

        // stage h (4 rows, coalesced float4)
        if (tid < 256)
            ((float4*)&sm.b2.h[0][0])[tid] = ((const float4*)(g_h + r0 * DD))[tid];
        __syncthreads();

        {
            const int kg   = tid >> 5;               // 0..15, 16 k each
            const int lane = tid & 31;
            const int rq   = lane >> 3;              // row 0..3
            const int f4c  = lane & 7;               // float4 col
            const int cf4  = cg_ * 8 + f4c;
            const float4* W2v = (const float4*)W2;

            float4 acc = make_float4(0.f, 0.f, 0.f, 0.f);
            #pragma unroll
            for (int kk = 0; kk < 16; kk++) {
                const int k = kg * 16 + kk;
                const float4 w = W2v[k * (DD / 4) + cf4];   // 8 distinct/warp, L1-reused
                const float  s = sm.b2.h[rq][k];
                acc.x = fmaf(s, w.x, acc.x);
                acc.y = fmaf(s, w.y, acc.y);
                acc.z = fmaf(s, w.z, acc.z);
                acc.w = fmaf(s, w.w, acc.w);
            }
            sm.b2.part[kg][rq][f4c] = acc;
        }
        __syncthreads();

        if (tid < 128) {
            const int r = tid >> 5, c = tid & 31;
            float s = b2[c0 + c];
            #pragma unroll
            for (int g = 0; g < 16; g++)
                s += ((const float*)&sm.b2.part[g][r][c >> 2])[c & 3];
            out[(r0 + r) * DD + c0 + c] = fmaxf(s, 0.f);
        }
    }
}

extern "C" void kernel_launch(void* const* d_in, const int* in_sizes, int n_in,
                              void* d_out, int out_size)
{
    const int*   X    = (const int*)d_in[0];
    const int*   vlen = (const int*)d_in[1];
    const float* emb  = (const float*)d_in[2];
    const float* W1   = (const float*)d_in[3];
    const float* b1   = (const float*)d_in[4];
    const float* W2   = (const float*)d_in[5];
    const float* b2   = (const float*)d_in[6];
    float*       out  = (float*)d_out;

    void* args[] = { (void*)&X, (void*)&vlen, (void*)&emb, (void*)&W1,
                     (void*)&b1, (void*)&W2, (void*)&b2, (void*)&out };
    cudaLaunchCooperativeKernel((void*)prot_net_coop,
                                dim3(GRID), dim3(NT), args, 0, (cudaStream_t)0);
}